// round 3
// baseline (speedup 1.0000x reference)
#include <cuda_runtime.h>

// Problem constants
#define NNODES   100000
#define NEDGES   30000
#define DFEAT    64
#define NEG_SLOPE 0.2f

// Scratch (device globals: allocation-free)
__device__ float  g_A [NEDGES * DFEAT];   // input-space edge accumulators
__device__ float2 g_cc[NEDGES];           // {sum(degV), count}
__device__ float  g_Xe[NEDGES * DFEAT];   // per-edge output features

// ---------------------------------------------------------------------------
// K0: zero accumulators
// ---------------------------------------------------------------------------
__global__ __launch_bounds__(256) void k_zero()
{
    int stride = gridDim.x * blockDim.x;
    for (int i = blockIdx.x * blockDim.x + threadIdx.x; i < NEDGES * DFEAT; i += stride)
        g_A[i] = 0.f;
    for (int j = blockIdx.x * blockDim.x + threadIdx.x; j < NEDGES; j += stride)
        g_cc[j] = make_float2(0.f, 0.f);
}

// ---------------------------------------------------------------------------
// K1: X0 = X @ Ww[0]^T + Wb[0]  -> out (used as Xv accumulator)
// 64 rows / block, 4 threads per row x 16 cols each.
// ---------------------------------------------------------------------------
__global__ __launch_bounds__(256) void k_x0(
    const float* __restrict__ X, const float* __restrict__ Ww,
    const float* __restrict__ Wb, float* __restrict__ out, int n_rows)
{
    __shared__ float WsT[64 * 64];    // WsT[i*64+o] = W[o][i]
    __shared__ float Xs [64 * 68];    // padded stride: conflict-free row reads
    int tid = threadIdx.x;
    for (int k = tid; k < 4096; k += 256) {
        int o = k >> 6, i = k & 63;
        WsT[i * 64 + o] = Ww[o * 64 + i];
    }
    int row0 = blockIdx.x * 64;
    for (int k = tid; k < 1024; k += 256) {
        int r = k >> 4, j = k & 15;
        int row = row0 + r;
        float4 v = make_float4(0.f, 0.f, 0.f, 0.f);
        if (row < n_rows) v = ((const float4*)X)[(size_t)row * 16 + j];
        ((float4*)(Xs + r * 68))[j] = v;
    }
    __syncthreads();

    int r = tid >> 2, cg = tid & 3;
    int row = row0 + r;
    float acc[16];
#pragma unroll
    for (int q = 0; q < 16; q++) acc[q] = 0.f;
    const float* xr = Xs + r * 68;
#pragma unroll 8
    for (int i = 0; i < 64; i++) {
        float xv = xr[i];
        const float4* wr = (const float4*)(WsT + i * 64 + cg * 16);
#pragma unroll
        for (int q = 0; q < 4; q++) {
            float4 w = wr[q];
            acc[q * 4 + 0] += xv * w.x;
            acc[q * 4 + 1] += xv * w.y;
            acc[q * 4 + 2] += xv * w.z;
            acc[q * 4 + 3] += xv * w.w;
        }
    }
    if (row < n_rows) {
#pragma unroll
        for (int q = 0; q < 4; q++) {
            int c = cg * 16 + q * 4;
            float4 o4;
            o4.x = acc[q * 4 + 0] + Wb[c + 0];
            o4.y = acc[q * 4 + 1] + Wb[c + 1];
            o4.z = acc[q * 4 + 2] + Wb[c + 2];
            o4.w = acc[q * 4 + 3] + Wb[c + 3];
            ((float4*)(out + (size_t)row * 64))[cg * 4 + q] = o4;
        }
    }
}

// ---------------------------------------------------------------------------
// K2: input-space scatter:  A[e] += degV[t_e][v] * X[v],  cc[e] += {deg, 1}
// 16 lanes per pair, float4 gather per lane, 4 scalar REDs per lane.
// ---------------------------------------------------------------------------
__global__ __launch_bounds__(256) void k_scatter1(
    const float* __restrict__ X, const float* __restrict__ degV,
    const int* __restrict__ vertex, const int* __restrict__ edges,
    int n_pairs)
{
    int gid      = (blockIdx.x * blockDim.x + threadIdx.x) >> 4;
    int l        = threadIdx.x & 15;
    int n_groups = (gridDim.x * blockDim.x) >> 4;
    for (int p = gid; p < n_pairs; p += n_groups) {
        int v = vertex[p];
        int e = edges[p];
        int t = e / 10000;
        float deg = degV[t * NNODES + v];
        float4 x = ((const float4*)(X + (size_t)v * 64))[l];
        float* dst = g_A + (size_t)e * 64 + l * 4;
        atomicAdd(dst + 0, x.x * deg);
        atomicAdd(dst + 1, x.y * deg);
        atomicAdd(dst + 2, x.z * deg);
        atomicAdd(dst + 3, x.w * deg);
        if (l == 0) {
            atomicAdd(&g_cc[e].x, deg);
            atomicAdd(&g_cc[e].y, 1.0f);
        }
    }
}

// ---------------------------------------------------------------------------
// K3: per-edge transform: Xe[e] = (W_{t+1} @ A[e] + b_{t+1}*sumdeg[e]) / max(cnt,1)
// 157 chunks of 64 edges per type -> every block is single-type.
// ---------------------------------------------------------------------------
__global__ __launch_bounds__(256) void k_edge(
    const float* __restrict__ Ww, const float* __restrict__ Wb)
{
    const int CHUNKS = 157;                 // ceil(10000/64)
    int t     = blockIdx.x / CHUNKS;
    int chunk = blockIdx.x % CHUNKS;
    int base  = t * 10000 + chunk * 64;
    int limit = (t + 1) * 10000;

    __shared__ float WsT[64 * 64];
    __shared__ float As [64 * 68];
    const float* W = Ww + (size_t)(t + 1) * 4096;
    const float* b = Wb + (size_t)(t + 1) * 64;
    int tid = threadIdx.x;
    for (int k = tid; k < 4096; k += 256) {
        int o = k >> 6, i = k & 63;
        WsT[i * 64 + o] = W[o * 64 + i];
    }
    for (int k = tid; k < 1024; k += 256) {
        int r = k >> 4, j = k & 15;
        int e = base + r;
        float4 v = make_float4(0.f, 0.f, 0.f, 0.f);
        if (e < limit) v = ((const float4*)(g_A))[(size_t)e * 16 + j];
        ((float4*)(As + r * 68))[j] = v;
    }
    __syncthreads();

    int r = tid >> 2, cg = tid & 3;
    int e = base + r;
    float acc[16];
#pragma unroll
    for (int q = 0; q < 16; q++) acc[q] = 0.f;
    const float* ar = As + r * 68;
#pragma unroll 8
    for (int i = 0; i < 64; i++) {
        float av = ar[i];
        const float4* wr = (const float4*)(WsT + i * 64 + cg * 16);
#pragma unroll
        for (int q = 0; q < 4; q++) {
            float4 w = wr[q];
            acc[q * 4 + 0] += av * w.x;
            acc[q * 4 + 1] += av * w.y;
            acc[q * 4 + 2] += av * w.z;
            acc[q * 4 + 3] += av * w.w;
        }
    }
    if (e < limit) {
        float2 c = g_cc[e];
        float inv = 1.0f / fmaxf(c.y, 1.0f);
#pragma unroll
        for (int q = 0; q < 4; q++) {
            int col = cg * 16 + q * 4;
            float4 o4;
            o4.x = (acc[q * 4 + 0] + b[col + 0] * c.x) * inv;
            o4.y = (acc[q * 4 + 1] + b[col + 1] * c.x) * inv;
            o4.z = (acc[q * 4 + 2] + b[col + 2] * c.x) * inv;
            o4.w = (acc[q * 4 + 3] + b[col + 3] * c.x) * inv;
            ((float4*)(g_Xe + (size_t)e * 64))[cg * 4 + q] = o4;
        }
    }
}

// ---------------------------------------------------------------------------
// K4: vertex scatter:  out[v] += Xe[e]   (out already holds X0)
// ---------------------------------------------------------------------------
__global__ __launch_bounds__(256) void k_scatter2(
    const int* __restrict__ vertex, const int* __restrict__ edges,
    float* __restrict__ out, int n_pairs)
{
    int gid      = (blockIdx.x * blockDim.x + threadIdx.x) >> 4;
    int l        = threadIdx.x & 15;
    int n_groups = (gridDim.x * blockDim.x) >> 4;
    for (int p = gid; p < n_pairs; p += n_groups) {
        int v = vertex[p];
        int e = edges[p];
        float4 x = ((const float4*)(g_Xe + (size_t)e * 64))[l];
        float* dst = out + (size_t)v * 64 + l * 4;
        atomicAdd(dst + 0, x.x);
        atomicAdd(dst + 1, x.y);
        atomicAdd(dst + 2, x.z);
        atomicAdd(dst + 3, x.w);
    }
}

// ---------------------------------------------------------------------------
// K5: row L2-normalize + leaky relu (warp per row, float2 per lane)
// ---------------------------------------------------------------------------
__global__ __launch_bounds__(256) void k_norm(float* __restrict__ out, int n_rows)
{
    int warp = (blockIdx.x * blockDim.x + threadIdx.x) >> 5;
    int lane = threadIdx.x & 31;
    if (warp >= n_rows) return;
    float2* row = (float2*)(out + (size_t)warp * 64);
    float2 a = row[lane];
    float s = a.x * a.x + a.y * a.y;
#pragma unroll
    for (int o = 16; o > 0; o >>= 1)
        s += __shfl_xor_sync(0xFFFFFFFFu, s, o);
    float rn = sqrtf(s);
    float scale = (rn == 0.0f) ? 0.0f : 1.0f / rn;
    float x = a.x * scale;
    float y = a.y * scale;
    x = (x >= 0.0f) ? x : NEG_SLOPE * x;
    y = (y >= 0.0f) ? y : NEG_SLOPE * y;
    row[lane] = make_float2(x, y);
}

// ---------------------------------------------------------------------------
extern "C" void kernel_launch(void* const* d_in, const int* in_sizes, int n_in,
                              void* d_out, int out_size)
{
    const float* X      = (const float*)d_in[0];   // [100000, 64] f32
    const float* degV   = (const float*)d_in[1];   // [3, 100000, 1] f32
    const float* Ww     = (const float*)d_in[2];   // [4, 64, 64] f32
    const float* Wb     = (const float*)d_in[3];   // [4, 64] f32
    const int*   vertex = (const int*)d_in[4];     // [1.6M] int32 (JAX x64 disabled)
    const int*   edges  = (const int*)d_in[5];     // [1.6M] int32
    float*       out    = (float*)d_out;           // [100000, 64] f32

    int n_pairs = in_sizes[4];
    int n_rows  = NNODES;

    k_zero<<<1024, 256>>>();
    k_x0<<<(n_rows + 63) / 64, 256>>>(X, Ww, Wb, out, n_rows);
    k_scatter1<<<1184, 256>>>(X, degV, vertex, edges, n_pairs);
    k_edge<<<3 * 157, 256>>>(Ww, Wb);
    k_scatter2<<<1184, 256>>>(vertex, edges, out, n_pairs);
    k_norm<<<(n_rows * 32 + 255) / 256, 256>>>(out, n_rows);
}

// round 4
// speedup vs baseline: 1.9430x; 1.9430x over previous
#include <cuda_runtime.h>

// Problem constants
#define NNODES   100000
#define NEDGES   30000
#define DFEAT    64
#define NEG_SLOPE 0.2f

// Scratch (device globals: allocation-free)
__device__ float  g_A [NEDGES * DFEAT];   // input-space edge accumulators
__device__ float2 g_cc[NEDGES];           // {sum(degV), count}
__device__ float  g_Xe[NEDGES * DFEAT];   // per-edge output features

// ---------------------------------------------------------------------------
// K0: zero accumulators
// ---------------------------------------------------------------------------
__global__ __launch_bounds__(256) void k_zero()
{
    int stride = gridDim.x * blockDim.x;
    for (int i = blockIdx.x * blockDim.x + threadIdx.x; i < NEDGES * DFEAT; i += stride)
        g_A[i] = 0.f;
    for (int j = blockIdx.x * blockDim.x + threadIdx.x; j < NEDGES; j += stride)
        g_cc[j] = make_float2(0.f, 0.f);
}

// ---------------------------------------------------------------------------
// K1: X0 = X @ Ww[0]^T + Wb[0]  -> out (used as Xv accumulator)
// ---------------------------------------------------------------------------
__global__ __launch_bounds__(256) void k_x0(
    const float* __restrict__ X, const float* __restrict__ Ww,
    const float* __restrict__ Wb, float* __restrict__ out, int n_rows)
{
    __shared__ float WsT[64 * 64];    // WsT[i*64+o] = W[o][i]
    __shared__ float Xs [64 * 68];    // padded stride: conflict-free row reads
    int tid = threadIdx.x;
    for (int k = tid; k < 4096; k += 256) {
        int o = k >> 6, i = k & 63;
        WsT[i * 64 + o] = Ww[o * 64 + i];
    }
    int row0 = blockIdx.x * 64;
    for (int k = tid; k < 1024; k += 256) {
        int r = k >> 4, j = k & 15;
        int row = row0 + r;
        float4 v = make_float4(0.f, 0.f, 0.f, 0.f);
        if (row < n_rows) v = ((const float4*)X)[(size_t)row * 16 + j];
        ((float4*)(Xs + r * 68))[j] = v;
    }
    __syncthreads();

    int r = tid >> 2, cg = tid & 3;
    int row = row0 + r;
    float acc[16];
#pragma unroll
    for (int q = 0; q < 16; q++) acc[q] = 0.f;
    const float* xr = Xs + r * 68;
#pragma unroll 8
    for (int i = 0; i < 64; i++) {
        float xv = xr[i];
        const float4* wr = (const float4*)(WsT + i * 64 + cg * 16);
#pragma unroll
        for (int q = 0; q < 4; q++) {
            float4 w = wr[q];
            acc[q * 4 + 0] += xv * w.x;
            acc[q * 4 + 1] += xv * w.y;
            acc[q * 4 + 2] += xv * w.z;
            acc[q * 4 + 3] += xv * w.w;
        }
    }
    if (row < n_rows) {
#pragma unroll
        for (int q = 0; q < 4; q++) {
            int c = cg * 16 + q * 4;
            float4 o4;
            o4.x = acc[q * 4 + 0] + Wb[c + 0];
            o4.y = acc[q * 4 + 1] + Wb[c + 1];
            o4.z = acc[q * 4 + 2] + Wb[c + 2];
            o4.w = acc[q * 4 + 3] + Wb[c + 3];
            ((float4*)(out + (size_t)row * 64))[cg * 4 + q] = o4;
        }
    }
}

// ---------------------------------------------------------------------------
// K2: input-space scatter:  A[e] += degV[t_e][v] * X[v],  cc[e] += {deg, 1}
// 16 lanes per pair, float4 gather + 1 vector RED per lane.
// ---------------------------------------------------------------------------
__global__ __launch_bounds__(256) void k_scatter1(
    const float* __restrict__ X, const float* __restrict__ degV,
    const int* __restrict__ vertex, const int* __restrict__ edges,
    int n_pairs)
{
    int gid      = (blockIdx.x * blockDim.x + threadIdx.x) >> 4;
    int l        = threadIdx.x & 15;
    int n_groups = (gridDim.x * blockDim.x) >> 4;
    for (int p = gid; p < n_pairs; p += n_groups) {
        int v = vertex[p];
        int e = edges[p];
        int t = e / 10000;
        float deg = degV[t * NNODES + v];
        float4 x = ((const float4*)(X + (size_t)v * 64))[l];
        float* dst = g_A + (size_t)e * 64 + l * 4;
        asm volatile("red.global.add.v4.f32 [%0], {%1,%2,%3,%4};"
                     :: "l"(dst), "f"(x.x * deg), "f"(x.y * deg),
                        "f"(x.z * deg), "f"(x.w * deg) : "memory");
        if (l == 0) {
            asm volatile("red.global.add.v2.f32 [%0], {%1,%2};"
                         :: "l"((float*)(g_cc + e)), "f"(deg), "f"(1.0f) : "memory");
        }
    }
}

// ---------------------------------------------------------------------------
// K3: per-edge transform: Xe[e] = (W_{t+1} @ A[e] + b_{t+1}*sumdeg[e]) / max(cnt,1)
// 157 chunks of 64 edges per type -> every block is single-type.
// ---------------------------------------------------------------------------
__global__ __launch_bounds__(256) void k_edge(
    const float* __restrict__ Ww, const float* __restrict__ Wb)
{
    const int CHUNKS = 157;                 // ceil(10000/64)
    int t     = blockIdx.x / CHUNKS;
    int chunk = blockIdx.x % CHUNKS;
    int base  = t * 10000 + chunk * 64;
    int limit = (t + 1) * 10000;

    __shared__ float WsT[64 * 64];
    __shared__ float As [64 * 68];
    const float* W = Ww + (size_t)(t + 1) * 4096;
    const float* b = Wb + (size_t)(t + 1) * 64;
    int tid = threadIdx.x;
    for (int k = tid; k < 4096; k += 256) {
        int o = k >> 6, i = k & 63;
        WsT[i * 64 + o] = W[o * 64 + i];
    }
    for (int k = tid; k < 1024; k += 256) {
        int r = k >> 4, j = k & 15;
        int e = base + r;
        float4 v = make_float4(0.f, 0.f, 0.f, 0.f);
        if (e < limit) v = ((const float4*)(g_A))[(size_t)e * 16 + j];
        ((float4*)(As + r * 68))[j] = v;
    }
    __syncthreads();

    int r = tid >> 2, cg = tid & 3;
    int e = base + r;
    float acc[16];
#pragma unroll
    for (int q = 0; q < 16; q++) acc[q] = 0.f;
    const float* ar = As + r * 68;
#pragma unroll 8
    for (int i = 0; i < 64; i++) {
        float av = ar[i];
        const float4* wr = (const float4*)(WsT + i * 64 + cg * 16);
#pragma unroll
        for (int q = 0; q < 4; q++) {
            float4 w = wr[q];
            acc[q * 4 + 0] += av * w.x;
            acc[q * 4 + 1] += av * w.y;
            acc[q * 4 + 2] += av * w.z;
            acc[q * 4 + 3] += av * w.w;
        }
    }
    if (e < limit) {
        float2 c = g_cc[e];
        float inv = 1.0f / fmaxf(c.y, 1.0f);
#pragma unroll
        for (int q = 0; q < 4; q++) {
            int col = cg * 16 + q * 4;
            float4 o4;
            o4.x = (acc[q * 4 + 0] + b[col + 0] * c.x) * inv;
            o4.y = (acc[q * 4 + 1] + b[col + 1] * c.x) * inv;
            o4.z = (acc[q * 4 + 2] + b[col + 2] * c.x) * inv;
            o4.w = (acc[q * 4 + 3] + b[col + 3] * c.x) * inv;
            ((float4*)(g_Xe + (size_t)e * 64))[cg * 4 + q] = o4;
        }
    }
}

// ---------------------------------------------------------------------------
// K4: vertex scatter:  out[v] += Xe[e]   (out already holds X0)
// ---------------------------------------------------------------------------
__global__ __launch_bounds__(256) void k_scatter2(
    const int* __restrict__ vertex, const int* __restrict__ edges,
    float* __restrict__ out, int n_pairs)
{
    int gid      = (blockIdx.x * blockDim.x + threadIdx.x) >> 4;
    int l        = threadIdx.x & 15;
    int n_groups = (gridDim.x * blockDim.x) >> 4;
    for (int p = gid; p < n_pairs; p += n_groups) {
        int v = vertex[p];
        int e = edges[p];
        float4 x = ((const float4*)(g_Xe + (size_t)e * 64))[l];
        float* dst = out + (size_t)v * 64 + l * 4;
        asm volatile("red.global.add.v4.f32 [%0], {%1,%2,%3,%4};"
                     :: "l"(dst), "f"(x.x), "f"(x.y), "f"(x.z), "f"(x.w)
                     : "memory");
    }
}

// ---------------------------------------------------------------------------
// K5: row L2-normalize + leaky relu (warp per row, float2 per lane)
// ---------------------------------------------------------------------------
__global__ __launch_bounds__(256) void k_norm(float* __restrict__ out, int n_rows)
{
    int warp = (blockIdx.x * blockDim.x + threadIdx.x) >> 5;
    int lane = threadIdx.x & 31;
    if (warp >= n_rows) return;
    float2* row = (float2*)(out + (size_t)warp * 64);
    float2 a = row[lane];
    float s = a.x * a.x + a.y * a.y;
#pragma unroll
    for (int o = 16; o > 0; o >>= 1)
        s += __shfl_xor_sync(0xFFFFFFFFu, s, o);
    float rn = sqrtf(s);
    float scale = (rn == 0.0f) ? 0.0f : 1.0f / rn;
    float x = a.x * scale;
    float y = a.y * scale;
    x = (x >= 0.0f) ? x : NEG_SLOPE * x;
    y = (y >= 0.0f) ? y : NEG_SLOPE * y;
    row[lane] = make_float2(x, y);
}

// ---------------------------------------------------------------------------
extern "C" void kernel_launch(void* const* d_in, const int* in_sizes, int n_in,
                              void* d_out, int out_size)
{
    const float* X      = (const float*)d_in[0];   // [100000, 64] f32
    const float* degV   = (const float*)d_in[1];   // [3, 100000, 1] f32
    const float* Ww     = (const float*)d_in[2];   // [4, 64, 64] f32
    const float* Wb     = (const float*)d_in[3];   // [4, 64] f32
    const int*   vertex = (const int*)d_in[4];     // [1.6M] int32
    const int*   edges  = (const int*)d_in[5];     // [1.6M] int32
    float*       out    = (float*)d_out;           // [100000, 64] f32

    int n_pairs = in_sizes[4];
    int n_rows  = NNODES;

    k_zero<<<1024, 256>>>();
    k_x0<<<(n_rows + 63) / 64, 256>>>(X, Ww, Wb, out, n_rows);
    k_scatter1<<<1184, 256>>>(X, degV, vertex, edges, n_pairs);
    k_edge<<<3 * 157, 256>>>(Ww, Wb);
    k_scatter2<<<1184, 256>>>(vertex, edges, out, n_pairs);
    k_norm<<<(n_rows * 32 + 255) / 256, 256>>>(out, n_rows);
}